// round 7
// baseline (speedup 1.0000x reference)
#include <cuda_runtime.h>
#include <cuda_bf16.h>
#include <cstdint>
#include <cmath>

// ============================================================================
// Inputs are FLOAT32 (bf16 values widened by the harness bridge) — proven by
// round-6 hex dumps. K=2048, R=32768, out_size=R*K+R => fp32 concat output
// [q as f32 | scale].
//
// k1: convert x f32 -> bf16 (lossless; values are exactly bf16)
// k2: transpose+convert h -> bf16 ht[n][k]
// k3: HMMA mma.sync GEMM (128x256 CTA tile, 3-stage cp.async, fused absmax)
// k4: quantize -> d_out
// ============================================================================

// scratch (device globals: allocation-guard-safe)
__device__ __nv_bfloat16 g_xb[(size_t)67108864];        // 134 MB x as bf16
__device__ __nv_bfloat16 g_ht[(size_t)2048 * 2048];     // 8 MB h^T as bf16
__device__ float        g_y[(size_t)67108864];          // 268 MB fp32 y
__device__ unsigned     g_absmax[32768];                // per-row absmax bits

static constexpr int MT = 128, NT = 256, KC = 64, STAGES = 3;
static constexpr int A_STAGE_BYTES = MT * KC * 2;           // 16384
static constexpr int B_STAGE_BYTES = NT * KC * 2;           // 32768
static constexpr int SMEM_B_BASE = STAGES * A_STAGE_BYTES;  // 49152
static constexpr int SMEM_TOTAL = STAGES * (A_STAGE_BYTES + B_STAGE_BYTES);

__device__ __forceinline__ uint32_t smem_u32(const void* p) {
    uint32_t a;
    asm("{ .reg .u64 t; cvta.to.shared.u64 t, %1; cvt.u32.u64 %0, t; }"
        : "=r"(a) : "l"(p));
    return a;
}
__device__ __forceinline__ uint32_t swz(uint32_t off) {
    return off ^ ((off >> 3) & 0x70u);
}
__device__ __forceinline__ void cp_async16(uint32_t s_addr, const void* g_addr) {
    asm volatile("cp.async.cg.shared.global [%0], [%1], 16;"
                 :: "r"(s_addr), "l"(g_addr) : "memory");
}
#define CP_COMMIT() asm volatile("cp.async.commit_group;" ::: "memory")
#define CP_WAIT(n)  asm volatile("cp.async.wait_group %0;" :: "n"(n) : "memory")

__device__ __forceinline__ void ldmatrix_x4(uint32_t* r, uint32_t addr) {
    asm volatile("ldmatrix.sync.aligned.m8n8.x4.shared.b16 {%0,%1,%2,%3}, [%4];"
                 : "=r"(r[0]), "=r"(r[1]), "=r"(r[2]), "=r"(r[3]) : "r"(addr));
}
__device__ __forceinline__ void mma_16816(float* d, const uint32_t* a,
                                          uint32_t b0, uint32_t b1) {
    asm volatile(
        "mma.sync.aligned.m16n8k16.row.col.f32.bf16.bf16.f32 "
        "{%0,%1,%2,%3}, {%4,%5,%6,%7}, {%8,%9}, {%0,%1,%2,%3};"
        : "+f"(d[0]), "+f"(d[1]), "+f"(d[2]), "+f"(d[3])
        : "r"(a[0]), "r"(a[1]), "r"(a[2]), "r"(a[3]), "r"(b0), "r"(b1));
}

// ============================================================================
// k0: zero absmax (graph replays reuse the scratch)
// ============================================================================
__global__ void zero_absmax_kernel(int R) {
    int i = blockIdx.x * blockDim.x + threadIdx.x;
    if (i < R) g_absmax[i] = 0u;
}

// ============================================================================
// k1: convert x (f32 -> bf16), 8 elems/thread, vectorized
// ============================================================================
__global__ void __launch_bounds__(256) convert_x_kernel(
    const float4* __restrict__ xf, long long n4) {
    long long i = (long long)blockIdx.x * blockDim.x + threadIdx.x;
    // each thread: 2 float4 = 8 floats -> 8 bf16 (16 B)
    long long base = i * 2;
    if (base + 1 < n4) {
        float4 v0 = xf[base + 0];
        float4 v1 = xf[base + 1];
        __nv_bfloat16 o[8] = {
            __float2bfloat16(v0.x), __float2bfloat16(v0.y),
            __float2bfloat16(v0.z), __float2bfloat16(v0.w),
            __float2bfloat16(v1.x), __float2bfloat16(v1.y),
            __float2bfloat16(v1.z), __float2bfloat16(v1.w)};
        *reinterpret_cast<uint4*>(&g_xb[base * 4]) =
            *reinterpret_cast<const uint4*>(o);
    }
}

// ============================================================================
// k2: transpose h [K][K] f32 -> g_ht [n][k] bf16
// ============================================================================
__global__ void transpose_h_kernel(const float* __restrict__ h, int K) {
    __shared__ float tile[32][33];
    int x = blockIdx.x * 32 + threadIdx.x;
    int y = blockIdx.y * 32 + threadIdx.y;
#pragma unroll
    for (int j = 0; j < 32; j += 8)
        tile[threadIdx.y + j][threadIdx.x] = h[(size_t)(y + j) * K + x];
    __syncthreads();
    int xo = blockIdx.y * 32 + threadIdx.x;
    int yo = blockIdx.x * 32 + threadIdx.y;
#pragma unroll
    for (int j = 0; j < 32; j += 8)
        g_ht[(size_t)(yo + j) * K + xo] =
            __float2bfloat16(tile[threadIdx.x][threadIdx.y + j]);
}

// ============================================================================
// k3: HMMA GEMM + fused row absmax. 8 warps = 2(M) x 4(N), warp tile 64x64.
// ============================================================================
__device__ __forceinline__ void load_stage(uint32_t sA, uint32_t sB,
                                           const __nv_bfloat16* a_src,
                                           const __nv_bfloat16* b_src,
                                           int tid, int K) {
#pragma unroll
    for (int i = 0; i < 4; i++) {
        int idx = tid + i * 256;
        int row = idx >> 3, c = idx & 7;
        uint32_t off = swz((uint32_t)row * 128u + (uint32_t)c * 16u);
        cp_async16(sA + off, a_src + (size_t)row * K + c * 8);
    }
#pragma unroll
    for (int i = 0; i < 8; i++) {
        int idx = tid + i * 256;
        int row = idx >> 3, c = idx & 7;
        uint32_t off = swz((uint32_t)row * 128u + (uint32_t)c * 16u);
        cp_async16(sB + off, b_src + (size_t)row * K + c * 8);
    }
}

__global__ void __launch_bounds__(256, 1) gemm_absmax_kernel(int K) {
    extern __shared__ char smem[];
    const uint32_t smem_base = smem_u32(smem);
    const int tid = threadIdx.x;
    const int wid = tid >> 5;
    const int lane = tid & 31;
    const int wm = wid >> 2;
    const int wn = wid & 3;

    const int m0 = blockIdx.y * MT;
    const int n0 = blockIdx.x * NT;
    const __nv_bfloat16* Ag = g_xb + (size_t)m0 * K;
    const __nv_bfloat16* Bg = g_ht + (size_t)n0 * K;

    float d[4][8][4];
#pragma unroll
    for (int mi = 0; mi < 4; mi++)
#pragma unroll
        for (int ni = 0; ni < 8; ni++)
#pragma unroll
            for (int j = 0; j < 4; j++) d[mi][ni][j] = 0.0f;

#pragma unroll
    for (int s = 0; s < STAGES - 1; s++) {
        load_stage(smem_base + s * A_STAGE_BYTES,
                   smem_base + SMEM_B_BASE + s * B_STAGE_BYTES,
                   Ag + s * KC, Bg + s * KC, tid, K);
        CP_COMMIT();
    }

    const int lrow = lane & 15;
    const int lkb  = (lane >> 4) * 8;
    const int NCHUNK = K / KC;

    for (int kc = 0; kc < NCHUNK; kc++) {
        CP_WAIT(STAGES - 2);
        __syncthreads();

        int knext = kc + STAGES - 1;
        if (knext < NCHUNK) {
            int s = knext % STAGES;
            load_stage(smem_base + s * A_STAGE_BYTES,
                       smem_base + SMEM_B_BASE + s * B_STAGE_BYTES,
                       Ag + knext * KC, Bg + knext * KC, tid, K);
        }
        CP_COMMIT();

        const int st = kc % STAGES;
        const uint32_t sA = smem_base + st * A_STAGE_BYTES;
        const uint32_t sB = smem_base + SMEM_B_BASE + st * B_STAGE_BYTES;

#pragma unroll
        for (int s = 0; s < KC / 16; s++) {
            uint32_t a[4][4], b[4][4];
#pragma unroll
            for (int mi = 0; mi < 4; mi++) {
                int row = wm * 64 + mi * 16 + lrow;
                uint32_t off = swz((uint32_t)row * 128u +
                                   (uint32_t)(s * 16 + lkb) * 2u);
                ldmatrix_x4(a[mi], sA + off);
            }
#pragma unroll
            for (int nj = 0; nj < 4; nj++) {
                int row = wn * 64 + nj * 16 + lrow;
                uint32_t off = swz((uint32_t)row * 128u +
                                   (uint32_t)(s * 16 + lkb) * 2u);
                ldmatrix_x4(b[nj], sB + off);
            }
#pragma unroll
            for (int mi = 0; mi < 4; mi++)
#pragma unroll
                for (int nj = 0; nj < 4; nj++) {
                    mma_16816(d[mi][2 * nj + 0], a[mi], b[nj][0], b[nj][2]);
                    mma_16816(d[mi][2 * nj + 1], a[mi], b[nj][1], b[nj][3]);
                }
        }
        __syncthreads();
    }

    // epilogue: fp32 y + per-row absmax (4-lane shfl reduce + atomicMax)
    const int g = lane >> 2;
    const int tc = (lane & 3) * 2;
#pragma unroll
    for (int mi = 0; mi < 4; mi++) {
#pragma unroll
        for (int half = 0; half < 2; half++) {
            int r = m0 + wm * 64 + mi * 16 + half * 8 + g;
            float* yrow = g_y + (size_t)r * K + n0 + wn * 64;
            float mx = 0.0f;
#pragma unroll
            for (int ni = 0; ni < 8; ni++) {
                float v0 = d[mi][ni][half * 2 + 0];
                float v1 = d[mi][ni][half * 2 + 1];
                mx = fmaxf(mx, fmaxf(fabsf(v0), fabsf(v1)));
                *reinterpret_cast<float2*>(yrow + ni * 8 + tc) =
                    make_float2(v0, v1);
            }
            mx = fmaxf(mx, __shfl_xor_sync(0xFFFFFFFFu, mx, 1));
            mx = fmaxf(mx, __shfl_xor_sync(0xFFFFFFFFu, mx, 2));
            if ((lane & 3) == 0)
                atomicMax(&g_absmax[r], __float_as_uint(mx));
        }
    }
}

// ============================================================================
// k4: quantize -> mode 0 fp32 concat [q_as_f32 | scale] (confirmed by
//     out_size = R*K + R). Other modes kept for robustness.
// ============================================================================
__global__ void __launch_bounds__(256) quant_kernel(void* __restrict__ d_out,
                                                    int K, long long R, int mode) {
    const int r = blockIdx.x;
    const int tid = threadIdx.x;
    const float amax = __uint_as_float(g_absmax[r]);
    const float scale = amax / 127.0f;
    const float safe = (scale == 0.0f) ? 1.0f : scale;
    const float inv = 1.0f / safe;

    const float4* yrow = reinterpret_cast<const float4*>(g_y + (size_t)r * K);
    const long long qelems = R * (long long)K;

    for (int i = tid; i < K / 4; i += 256) {
        float4 v = yrow[i];
        float vals[4] = {v.x, v.y, v.z, v.w};
        float q[4];
#pragma unroll
        for (int j = 0; j < 4; j++) {
            float t = rintf(vals[j] * inv);          // half-to-even, like jnp.round
            q[j] = fminf(fmaxf(t, -127.0f), 127.0f);
        }
        if (mode == 0) {
            float* out = reinterpret_cast<float*>(d_out) + (size_t)r * K + i * 4;
            *reinterpret_cast<float4*>(out) = make_float4(q[0], q[1], q[2], q[3]);
        } else {
            uint32_t p = (uint32_t)((int)q[0] & 0xFF) |
                         ((uint32_t)((int)q[1] & 0xFF) << 8) |
                         ((uint32_t)((int)q[2] & 0xFF) << 16) |
                         ((uint32_t)((int)q[3] & 0xFF) << 24);
            reinterpret_cast<uint32_t*>(
                reinterpret_cast<char*>(d_out) + (size_t)r * K)[i] = p;
        }
    }
    if (tid == 0) {
        if (mode == 0) {
            reinterpret_cast<float*>(d_out)[qelems + r] = scale;
        } else if (mode == 1) {
            float* sc = reinterpret_cast<float*>(
                reinterpret_cast<char*>(d_out) + qelems);
            sc[r] = scale;
        }
    }
}

// ============================================================================
// launcher (graph-capture clean: kernel launches only)
// ============================================================================
static int isqrt_ll(long long v) {
    long long r = (long long)sqrt((double)v);
    while (r * r > v) r--;
    while ((r + 1) * (r + 1) <= v) r++;
    return (int)r;
}

extern "C" void kernel_launch(void* const* d_in, const int* in_sizes, int n_in,
                              void* d_out, int out_size) {
    long long s0 = in_sizes[0], s1 = (n_in > 1) ? in_sizes[1] : 0;
    const void* xv; const void* hv;
    long long numel_x, numel_h;
    if (s0 >= s1) { xv = d_in[0]; numel_x = s0; hv = d_in[1]; numel_h = s1; }
    else          { xv = d_in[1]; numel_x = s1; hv = d_in[0]; numel_h = s0; }
    const int K = isqrt_ll(numel_h);        // 2048
    const long long R = numel_x / K;        // 32768
    const long long qelems = R * (long long)K;

    int mode;
    if ((long long)out_size == qelems + R)            mode = 0; // fp32 concat (confirmed)
    else if ((long long)out_size == qelems + 4LL * R) mode = 1;
    else                                              mode = 2;

    cudaFuncSetAttribute(gemm_absmax_kernel,
                         cudaFuncAttributeMaxDynamicSharedMemorySize, SMEM_TOTAL);

    zero_absmax_kernel<<<(unsigned)((R + 255) / 256), 256>>>((int)R);
    convert_x_kernel<<<(unsigned)((numel_x / 8 + 255) / 256), 256>>>(
        (const float4*)xv, numel_x / 4);
    transpose_h_kernel<<<dim3(K / 32, K / 32), dim3(32, 8)>>>((const float*)hv, K);
    gemm_absmax_kernel<<<dim3(K / NT, (unsigned)(R / MT)), 256, SMEM_TOTAL>>>(K);
    quant_kernel<<<(unsigned)R, 256>>>(d_out, K, R, mode);
}

// round 8
// speedup vs baseline: 1.0732x; 1.0732x over previous
#include <cuda_runtime.h>
#include <cuda_bf16.h>
#include <cstdint>
#include <cmath>

// ============================================================================
// Inputs: f32 (bf16-valued, widened by harness). K=2048, R=32768.
// Output mode 0: fp32 concat [q_as_f32 (R*K) | scale (R)].
//
// R7: GEMM was 802us @ tensor=56.5%, 2 barriers/iter, 3 stages, 1 CTA/SM.
// This round: 4-stage cp.async pipeline + ONE barrier per K-iteration
// (the post-wait barrier doubles as the write-target-drain barrier since the
// write stage at iter kc is (kc-1)%S = the stage whose compute just ended).
// ============================================================================

__device__ __nv_bfloat16 g_xb[(size_t)67108864];        // 134 MB x as bf16
__device__ __nv_bfloat16 g_ht[(size_t)2048 * 2048];     // 8 MB h^T as bf16
__device__ float        g_y[(size_t)67108864];          // 268 MB fp32 y
__device__ unsigned     g_absmax[32768];                // per-row absmax bits

static constexpr int MT = 128, NT = 256, KC = 64, STAGES = 4;
static constexpr int A_STAGE_BYTES = MT * KC * 2;           // 16384
static constexpr int B_STAGE_BYTES = NT * KC * 2;           // 32768
static constexpr int SMEM_B_BASE = STAGES * A_STAGE_BYTES;  // 65536
static constexpr int SMEM_TOTAL = STAGES * (A_STAGE_BYTES + B_STAGE_BYTES); // 196608

__device__ __forceinline__ uint32_t smem_u32(const void* p) {
    uint32_t a;
    asm("{ .reg .u64 t; cvta.to.shared.u64 t, %1; cvt.u32.u64 %0, t; }"
        : "=r"(a) : "l"(p));
    return a;
}
__device__ __forceinline__ uint32_t swz(uint32_t off) {
    return off ^ ((off >> 3) & 0x70u);
}
__device__ __forceinline__ void cp_async16(uint32_t s_addr, const void* g_addr) {
    asm volatile("cp.async.cg.shared.global [%0], [%1], 16;"
                 :: "r"(s_addr), "l"(g_addr) : "memory");
}
#define CP_COMMIT() asm volatile("cp.async.commit_group;" ::: "memory")
#define CP_WAIT(n)  asm volatile("cp.async.wait_group %0;" :: "n"(n) : "memory")

__device__ __forceinline__ void ldmatrix_x4(uint32_t* r, uint32_t addr) {
    asm volatile("ldmatrix.sync.aligned.m8n8.x4.shared.b16 {%0,%1,%2,%3}, [%4];"
                 : "=r"(r[0]), "=r"(r[1]), "=r"(r[2]), "=r"(r[3]) : "r"(addr));
}
__device__ __forceinline__ void mma_16816(float* d, const uint32_t* a,
                                          uint32_t b0, uint32_t b1) {
    asm volatile(
        "mma.sync.aligned.m16n8k16.row.col.f32.bf16.bf16.f32 "
        "{%0,%1,%2,%3}, {%4,%5,%6,%7}, {%8,%9}, {%0,%1,%2,%3};"
        : "+f"(d[0]), "+f"(d[1]), "+f"(d[2]), "+f"(d[3])
        : "r"(a[0]), "r"(a[1]), "r"(a[2]), "r"(a[3]), "r"(b0), "r"(b1));
}

__global__ void zero_absmax_kernel(int R) {
    int i = blockIdx.x * blockDim.x + threadIdx.x;
    if (i < R) g_absmax[i] = 0u;
}

__global__ void __launch_bounds__(256) convert_x_kernel(
    const float4* __restrict__ xf, long long n4) {
    long long i = (long long)blockIdx.x * blockDim.x + threadIdx.x;
    long long base = i * 2;
    if (base + 1 < n4) {
        float4 v0 = xf[base + 0];
        float4 v1 = xf[base + 1];
        __nv_bfloat16 o[8] = {
            __float2bfloat16(v0.x), __float2bfloat16(v0.y),
            __float2bfloat16(v0.z), __float2bfloat16(v0.w),
            __float2bfloat16(v1.x), __float2bfloat16(v1.y),
            __float2bfloat16(v1.z), __float2bfloat16(v1.w)};
        *reinterpret_cast<uint4*>(&g_xb[base * 4]) =
            *reinterpret_cast<const uint4*>(o);
    }
}

__global__ void transpose_h_kernel(const float* __restrict__ h, int K) {
    __shared__ float tile[32][33];
    int x = blockIdx.x * 32 + threadIdx.x;
    int y = blockIdx.y * 32 + threadIdx.y;
#pragma unroll
    for (int j = 0; j < 32; j += 8)
        tile[threadIdx.y + j][threadIdx.x] = h[(size_t)(y + j) * K + x];
    __syncthreads();
    int xo = blockIdx.y * 32 + threadIdx.x;
    int yo = blockIdx.x * 32 + threadIdx.y;
#pragma unroll
    for (int j = 0; j < 32; j += 8)
        g_ht[(size_t)(yo + j) * K + xo] =
            __float2bfloat16(tile[threadIdx.x][threadIdx.y + j]);
}

// ============================================================================
// GEMM + fused row absmax. 8 warps = 2(M) x 4(N), warp tile 64x64.
// 4-stage cp.async pipeline, single barrier per K-iteration.
// ============================================================================
__device__ __forceinline__ void load_stage(uint32_t sA, uint32_t sB,
                                           const __nv_bfloat16* a_src,
                                           const __nv_bfloat16* b_src,
                                           int tid, int K) {
#pragma unroll
    for (int i = 0; i < 4; i++) {
        int idx = tid + i * 256;
        int row = idx >> 3, c = idx & 7;
        uint32_t off = swz((uint32_t)row * 128u + (uint32_t)c * 16u);
        cp_async16(sA + off, a_src + (size_t)row * K + c * 8);
    }
#pragma unroll
    for (int i = 0; i < 8; i++) {
        int idx = tid + i * 256;
        int row = idx >> 3, c = idx & 7;
        uint32_t off = swz((uint32_t)row * 128u + (uint32_t)c * 16u);
        cp_async16(sB + off, b_src + (size_t)row * K + c * 8);
    }
}

__global__ void __launch_bounds__(256, 1) gemm_absmax_kernel(int K) {
    extern __shared__ char smem[];
    const uint32_t smem_base = smem_u32(smem);
    const int tid = threadIdx.x;
    const int wid = tid >> 5;
    const int lane = tid & 31;
    const int wm = wid >> 2;
    const int wn = wid & 3;

    const int m0 = blockIdx.y * MT;
    const int n0 = blockIdx.x * NT;
    const __nv_bfloat16* Ag = g_xb + (size_t)m0 * K;
    const __nv_bfloat16* Bg = g_ht + (size_t)n0 * K;

    float d[4][8][4];
#pragma unroll
    for (int mi = 0; mi < 4; mi++)
#pragma unroll
        for (int ni = 0; ni < 8; ni++)
#pragma unroll
            for (int j = 0; j < 4; j++) d[mi][ni][j] = 0.0f;

    // prologue: stages 0..STAGES-2
#pragma unroll
    for (int s = 0; s < STAGES - 1; s++) {
        load_stage(smem_base + s * A_STAGE_BYTES,
                   smem_base + SMEM_B_BASE + s * B_STAGE_BYTES,
                   Ag + s * KC, Bg + s * KC, tid, K);
        CP_COMMIT();
    }

    const int lrow = lane & 15;
    const int lkb  = (lane >> 4) * 8;
    const int NCHUNK = K / KC;   // 32

    for (int kc = 0; kc < NCHUNK; kc++) {
        CP_WAIT(STAGES - 2);
        // Single barrier: (a) stage kc now visible to all warps,
        // (b) all warps finished reading stage (kc-1)%S last iteration,
        //     which is exactly the write target of this iteration's loads.
        __syncthreads();

        int knext = kc + STAGES - 1;
        if (knext < NCHUNK) {
            int s = knext % STAGES;   // == (kc-1) % STAGES
            load_stage(smem_base + s * A_STAGE_BYTES,
                       smem_base + SMEM_B_BASE + s * B_STAGE_BYTES,
                       Ag + knext * KC, Bg + knext * KC, tid, K);
        }
        CP_COMMIT();

        const int st = kc % STAGES;
        const uint32_t sA = smem_base + st * A_STAGE_BYTES;
        const uint32_t sB = smem_base + SMEM_B_BASE + st * B_STAGE_BYTES;

#pragma unroll
        for (int s = 0; s < KC / 16; s++) {
            uint32_t a[4][4], b[4][4];
#pragma unroll
            for (int mi = 0; mi < 4; mi++) {
                int row = wm * 64 + mi * 16 + lrow;
                uint32_t off = swz((uint32_t)row * 128u +
                                   (uint32_t)(s * 16 + lkb) * 2u);
                ldmatrix_x4(a[mi], sA + off);
            }
#pragma unroll
            for (int nj = 0; nj < 4; nj++) {
                int row = wn * 64 + nj * 16 + lrow;
                uint32_t off = swz((uint32_t)row * 128u +
                                   (uint32_t)(s * 16 + lkb) * 2u);
                ldmatrix_x4(b[nj], sB + off);
            }
#pragma unroll
            for (int mi = 0; mi < 4; mi++)
#pragma unroll
                for (int nj = 0; nj < 4; nj++) {
                    mma_16816(d[mi][2 * nj + 0], a[mi], b[nj][0], b[nj][2]);
                    mma_16816(d[mi][2 * nj + 1], a[mi], b[nj][1], b[nj][3]);
                }
        }
    }

    // epilogue: fp32 y + per-row absmax (4-lane shfl reduce + atomicMax)
    const int g = lane >> 2;
    const int tc = (lane & 3) * 2;
#pragma unroll
    for (int mi = 0; mi < 4; mi++) {
#pragma unroll
        for (int half = 0; half < 2; half++) {
            int r = m0 + wm * 64 + mi * 16 + half * 8 + g;
            float* yrow = g_y + (size_t)r * K + n0 + wn * 64;
            float mx = 0.0f;
#pragma unroll
            for (int ni = 0; ni < 8; ni++) {
                float v0 = d[mi][ni][half * 2 + 0];
                float v1 = d[mi][ni][half * 2 + 1];
                mx = fmaxf(mx, fmaxf(fabsf(v0), fabsf(v1)));
                *reinterpret_cast<float2*>(yrow + ni * 8 + tc) =
                    make_float2(v0, v1);
            }
            mx = fmaxf(mx, __shfl_xor_sync(0xFFFFFFFFu, mx, 1));
            mx = fmaxf(mx, __shfl_xor_sync(0xFFFFFFFFu, mx, 2));
            if ((lane & 3) == 0)
                atomicMax(&g_absmax[r], __float_as_uint(mx));
        }
    }
}

// ============================================================================
// quantize. mode 0 = fp32 concat [q_as_f32 | scale] (confirmed for this
// instance); modes 1/2 kept for shape variants.
// ============================================================================
__global__ void __launch_bounds__(256) quant_kernel(void* __restrict__ d_out,
                                                    int K, long long R, int mode) {
    const int r = blockIdx.x;
    const int tid = threadIdx.x;
    const float amax = __uint_as_float(g_absmax[r]);
    const float scale = amax / 127.0f;
    const float safe = (scale == 0.0f) ? 1.0f : scale;
    const float inv = 1.0f / safe;

    const float4* yrow = reinterpret_cast<const float4*>(g_y + (size_t)r * K);
    const long long qelems = R * (long long)K;

    for (int i = tid; i < K / 4; i += 256) {
        float4 v = yrow[i];
        float vals[4] = {v.x, v.y, v.z, v.w};
        float q[4];
#pragma unroll
        for (int j = 0; j < 4; j++) {
            float t = rintf(vals[j] * inv);
            q[j] = fminf(fmaxf(t, -127.0f), 127.0f);
        }
        if (mode == 0) {
            float* out = reinterpret_cast<float*>(d_out) + (size_t)r * K + i * 4;
            *reinterpret_cast<float4*>(out) = make_float4(q[0], q[1], q[2], q[3]);
        } else {
            uint32_t p = (uint32_t)((int)q[0] & 0xFF) |
                         ((uint32_t)((int)q[1] & 0xFF) << 8) |
                         ((uint32_t)((int)q[2] & 0xFF) << 16) |
                         ((uint32_t)((int)q[3] & 0xFF) << 24);
            reinterpret_cast<uint32_t*>(
                reinterpret_cast<char*>(d_out) + (size_t)r * K)[i] = p;
        }
    }
    if (tid == 0) {
        if (mode == 0) {
            reinterpret_cast<float*>(d_out)[qelems + r] = scale;
        } else if (mode == 1) {
            float* sc = reinterpret_cast<float*>(
                reinterpret_cast<char*>(d_out) + qelems);
            sc[r] = scale;
        }
    }
}

// ============================================================================
// launcher (graph-capture clean)
// ============================================================================
static int isqrt_ll(long long v) {
    long long r = (long long)sqrt((double)v);
    while (r * r > v) r--;
    while ((r + 1) * (r + 1) <= v) r++;
    return (int)r;
}

extern "C" void kernel_launch(void* const* d_in, const int* in_sizes, int n_in,
                              void* d_out, int out_size) {
    long long s0 = in_sizes[0], s1 = (n_in > 1) ? in_sizes[1] : 0;
    const void* xv; const void* hv;
    long long numel_x, numel_h;
    if (s0 >= s1) { xv = d_in[0]; numel_x = s0; hv = d_in[1]; numel_h = s1; }
    else          { xv = d_in[1]; numel_x = s1; hv = d_in[0]; numel_h = s0; }
    const int K = isqrt_ll(numel_h);        // 2048
    const long long R = numel_x / K;        // 32768
    const long long qelems = R * (long long)K;

    int mode;
    if ((long long)out_size == qelems + R)            mode = 0;
    else if ((long long)out_size == qelems + 4LL * R) mode = 1;
    else                                              mode = 2;

    cudaFuncSetAttribute(gemm_absmax_kernel,
                         cudaFuncAttributeMaxDynamicSharedMemorySize, SMEM_TOTAL);

    zero_absmax_kernel<<<(unsigned)((R + 255) / 256), 256>>>((int)R);
    convert_x_kernel<<<(unsigned)((numel_x / 8 + 255) / 256), 256>>>(
        (const float4*)xv, numel_x / 4);
    transpose_h_kernel<<<dim3(K / 32, K / 32), dim3(32, 8)>>>((const float*)hv, K);
    gemm_absmax_kernel<<<dim3(K / NT, (unsigned)(R / MT)), 256, SMEM_TOTAL>>>(K);
    quant_kernel<<<(unsigned)R, 256>>>(d_out, K, R, mode);
}